// round 1
// baseline (speedup 1.0000x reference)
#include <cuda_runtime.h>

#define HH 1024
#define WW 1024
#define MM 512            // 16 segments * 32 samples
#define T_WIN 18.0f       // sigmoid transition half-window; tail err e^-18 = 1.5e-8

__global__ __launch_bounds__(256, 4)
void bvr_render_kernel(const float* __restrict__ cp,
                       const float* __restrict__ color,
                       float* __restrict__ out)
{
    __shared__ float2 s_pts[MM];
    __shared__ float  s_acc[WW];      // windowed sigmoid contributions
    __shared__ float  s_d[WW + 1];    // difference array for "full-w" prefix regions
    __shared__ float  s_part[256];
    __shared__ float  s_wsum[8];

    const int tid = threadIdx.x;
    const int y   = blockIdx.x;
    const float fy = (float)y;

    // ---- 1. Sample Bezier path points (recomputed per block; trivial cost) ----
    for (int i = tid; i < MM; i += 256) {
        int s = i >> 5;
        int j = i & 31;
        float t  = (float)j / 31.0f;     // j=31 -> exactly 1.0f
        float mt = 1.0f - t;
        float w0 = mt * mt * mt;
        float w1 = 3.0f * mt * mt * t;
        float w2 = 3.0f * mt * t * t;
        float w3 = t * t * t;
        const float* p = cp + 6 * s;     // control point 3s, stride 2 floats
        float px = w0 * p[0] + w1 * p[2] + w2 * p[4] + w3 * p[6];
        float py = w0 * p[1] + w1 * p[3] + w2 * p[5] + w3 * p[7];
        s_pts[i] = make_float2(px, py);
    }
    for (int i = tid; i < WW; i += 256) { s_acc[i] = 0.0f; s_d[i] = 0.0f; }
    if (tid == 0) s_d[WW] = 0.0f;
    __syncthreads();

    // ---- 2. Edge loop: each thread handles 2 edges for this row ----
    for (int e = tid; e < MM; e += 256) {
        float2 p0 = s_pts[e];
        float2 p1 = s_pts[(e + 1) & (MM - 1)];
        float dy = p1.y - p0.y;
        if (fabsf(dy) < 1e-6f) continue;            // coeff == 0
        float coeff = (dy > 0.0f) ? 1.0f : -1.0f;
        float dx = p1.x - p0.x;
        float t  = (fy - p0.y) / (dy + 1e-8f);      // matches reference exactly
        float v1 = 1.0f / (1.0f + __expf(-20.0f * t));
        float v2 = 1.0f / (1.0f + __expf(20.0f * (t - 1.0f)));
        float w  = coeff * v1 * v2;
        if (fabsf(w) < 1e-10f) continue;            // negligible (err <= 512e-10)

        float xc = p0.x + t * dx;                   // crossing x for this row
        if (xc + T_WIN < 0.0f) continue;            // sigmoid ~0 across whole row

        int xlo = (int)ceilf(xc - T_WIN);
        if (xlo < 0) xlo = 0;
        int xhi = (int)floorf(xc + T_WIN);
        if (xhi > WW - 1) xhi = WW - 1;

        // Full contribution w on [0, xlo): difference array
        atomicAdd(&s_d[0], w);
        int xsub = (xlo < WW) ? xlo : WW;
        atomicAdd(&s_d[xsub], -w);

        // Transition window: exact sigmoid via exp recurrence (1 MUFU/px)
        if (xlo <= xhi) {
            float sgrow = __expf((float)xlo - xc);  // exp(x - xc), grows by e each px
            const float E = 2.71828182845904523536f;
            for (int x = xlo; x <= xhi; ++x) {
                float val = __fdividef(w, 1.0f + sgrow);
                atomicAdd(&s_acc[x], val);
                sgrow *= E;
            }
        }
    }
    __syncthreads();

    // ---- 3. Inclusive prefix sum of s_d[0..1023] (256 threads x 4 elems) ----
    const int b = tid * 4;
    float v0 = s_d[b];
    float v1 = v0 + s_d[b + 1];
    float v2 = v1 + s_d[b + 2];
    float v3 = v2 + s_d[b + 3];
    s_part[tid] = v3;
    __syncthreads();

    float pscan = s_part[tid];
    const int lane = tid & 31;
    const int wrp  = tid >> 5;
    #pragma unroll
    for (int off = 1; off < 32; off <<= 1) {
        float n = __shfl_up_sync(0xffffffffu, pscan, off);
        if (lane >= off) pscan += n;
    }
    if (lane == 31) s_wsum[wrp] = pscan;
    __syncthreads();
    if (tid == 0) {
        float r = 0.0f;
        #pragma unroll
        for (int i = 0; i < 8; ++i) { r += s_wsum[i]; s_wsum[i] = r; }
    }
    __syncthreads();
    float woff = (wrp > 0) ? s_wsum[wrp - 1] : 0.0f;
    float excl = woff + pscan - v3;   // exclusive prefix before this thread's 4 elems

    // ---- 4. Alpha + output (float4 per pixel, coalesced) ----
    const float cr = color[0], cg = color[1], cb = color[2];
    float wind[4];
    wind[0] = excl + v0 + s_acc[b];
    wind[1] = excl + v1 + s_acc[b + 1];
    wind[2] = excl + v2 + s_acc[b + 2];
    wind[3] = excl + v3 + s_acc[b + 3];

    float4* orow = (float4*)out + (size_t)y * WW + b;
    #pragma unroll
    for (int k = 0; k < 4; ++k) {
        float a = 1.0f / (1.0f + __expf(-4.0f * wind[k]));
        orow[k] = make_float4(cr, cg, cb, a);
    }
}

extern "C" void kernel_launch(void* const* d_in, const int* in_sizes, int n_in,
                              void* d_out, int out_size)
{
    const float* cp    = (const float*)d_in[0];   // (49, 2) float32
    const float* color = (const float*)d_in[1];   // (3,)   float32
    float* out = (float*)d_out;                   // (1024, 1024, 4) float32
    (void)in_sizes; (void)n_in; (void)out_size;
    bvr_render_kernel<<<HH, 256>>>(cp, color, out);
}

// round 2
// speedup vs baseline: 2.9232x; 2.9232x over previous
#include <cuda_runtime.h>

#define HH 1024
#define WW 1024
#define MM 512            // 16 segments * 32 samples
#define T_WIN 18.0f       // sigmoid transition half-window; tail err e^-18 = 1.5e-8
#define WPIX 37           // max pixels in a transition window

// Per-edge precomputed constants (phase A -> phase B)
__device__ float4 g_edge[MM];   // x0, dx, rinv = 1/(dy+1e-8), coeff
__device__ float2 g_eyr[MM];    // ymin, ymax of rows where |w| can exceed 1e-10
__device__ float  g_ey0[MM];    // y0

// ---------------- Phase A: sample path, build edge tables ----------------
__global__ void bvr_prep_kernel(const float* __restrict__ cp)
{
    __shared__ float2 s_pts[MM];
    const int i = threadIdx.x;          // 512 threads

    // sample point i
    {
        int s = i >> 5;
        int j = i & 31;
        float t  = (float)j / 31.0f;
        float mt = 1.0f - t;
        float w0 = mt * mt * mt;
        float w1 = 3.0f * mt * mt * t;
        float w2 = 3.0f * mt * t * t;
        float w3 = t * t * t;
        const float* p = cp + 6 * s;
        float px = w0 * p[0] + w1 * p[2] + w2 * p[4] + w3 * p[6];
        float py = w0 * p[1] + w1 * p[3] + w2 * p[5] + w3 * p[7];
        s_pts[i] = make_float2(px, py);
    }
    __syncthreads();

    // edge i
    float2 p0 = s_pts[i];
    float2 p1 = s_pts[(i + 1) & (MM - 1)];
    float dy = p1.y - p0.y;

    if (fabsf(dy) < 1e-6f) {
        // inactive edge: impossible y-range
        g_eyr[i]  = make_float2(1e30f, -1e30f);
        g_edge[i] = make_float4(0.f, 0.f, 0.f, 0.f);
        g_ey0[i]  = 0.f;
        return;
    }
    float coeff = (dy > 0.0f) ? 1.0f : -1.0f;
    float dx   = p1.x - p0.x;
    float rinv = 1.0f / (dy + 1e-8f);
    // |w| > 1e-10 requires t in ~[-1.2, 2.2]
    float ya = p0.y - 1.2f * dy;
    float yb = p0.y + 2.2f * dy;
    g_eyr[i]  = make_float2(fminf(ya, yb), fmaxf(ya, yb));
    g_edge[i] = make_float4(p0.x, dx, rinv, coeff);
    g_ey0[i]  = p0.y;
}

// ---------------- Phase B: one block per row ----------------
__global__ __launch_bounds__(256)
void bvr_render_kernel(const float* __restrict__ color,
                       float* __restrict__ out)
{
    __shared__ float s_acc[WW];     // windowed sigmoid contributions
    __shared__ float s_w[MM];       // compacted active-edge weight
    __shared__ float s_xc[MM];      // compacted crossing x
    __shared__ int   s_xlo[MM];     // compacted window start (clamped to [0, WW])
    __shared__ int   s_cnt;

    const int tid = threadIdx.x;
    const int y   = blockIdx.x;
    const float fy = (float)y;

    if (tid == 0) s_cnt = 0;
    for (int i = tid; i < WW; i += 256) s_acc[i] = 0.0f;
    __syncthreads();

    // ---- compact active edges for this row ----
    for (int e = tid; e < MM; e += 256) {
        float2 yr = g_eyr[e];
        if (fy < yr.x || fy > yr.y) continue;       // ~95% of edges exit here

        float4 ed = g_edge[e];                       // x0, dx, rinv, coeff
        float y0  = g_ey0[e];
        float t   = (fy - y0) * ed.z;
        float v1  = 1.0f / (1.0f + __expf(-20.0f * t));
        float v2  = 1.0f / (1.0f + __expf(20.0f * (t - 1.0f)));
        float w   = ed.w * v1 * v2;
        if (fabsf(w) < 1e-10f) continue;

        float xc = ed.x + t * ed.y;
        if (xc + T_WIN < 0.0f) continue;            // contributes ~0 everywhere

        int xlo = (int)ceilf(xc - T_WIN);
        xlo = max(0, min(xlo, WW));                 // xlo==WW -> full-row base w

        int k = atomicAdd(&s_cnt, 1);
        s_w[k]   = w;
        s_xc[k]  = xc;
        s_xlo[k] = xlo;
    }
    __syncthreads();

    const int K = s_cnt;

    // ---- flattened (edge, window-pixel) work: balanced, no divergence ----
    for (int i = tid; i < K * WPIX; i += 256) {
        int k   = i / WPIX;
        int sub = i - k * WPIX;
        int xlo = s_xlo[k];
        int x   = xlo + sub;
        if (x >= WW) continue;
        float xc = s_xc[k];
        if ((float)x > xc + T_WIN) continue;        // past window end
        float val = __fdividef(s_w[k], 1.0f + __expf((float)x - xc));
        atomicAdd(&s_acc[x], val);
    }
    __syncthreads();

    // ---- base sum (columns fully left of each window get w) + output ----
    const int b = tid * 4;
    float w0 = 0.f, w1 = 0.f, w2 = 0.f, w3 = 0.f;
    for (int k = 0; k < K; ++k) {
        float wk  = s_w[k];                         // broadcast LDS
        int   xlo = s_xlo[k];
        if (b + 0 < xlo) w0 += wk;
        if (b + 1 < xlo) w1 += wk;
        if (b + 2 < xlo) w2 += wk;
        if (b + 3 < xlo) w3 += wk;
    }
    w0 += s_acc[b + 0];
    w1 += s_acc[b + 1];
    w2 += s_acc[b + 2];
    w3 += s_acc[b + 3];

    const float cr = __ldg(color + 0);
    const float cg = __ldg(color + 1);
    const float cb = __ldg(color + 2);

    float4* orow = (float4*)out + (size_t)y * WW + b;
    float wind[4] = {w0, w1, w2, w3};
    #pragma unroll
    for (int q = 0; q < 4; ++q) {
        float a = 1.0f / (1.0f + __expf(-4.0f * wind[q]));
        orow[q] = make_float4(cr, cg, cb, a);
    }
}

extern "C" void kernel_launch(void* const* d_in, const int* in_sizes, int n_in,
                              void* d_out, int out_size)
{
    const float* cp    = (const float*)d_in[0];   // (49, 2) float32
    const float* color = (const float*)d_in[1];   // (3,)   float32
    float* out = (float*)d_out;                   // (1024, 1024, 4) float32
    (void)in_sizes; (void)n_in; (void)out_size;
    bvr_prep_kernel<<<1, MM>>>(cp);
    bvr_render_kernel<<<HH, 256>>>(color, out);
}